// round 13
// baseline (speedup 1.0000x reference)
#include <cuda_runtime.h>

// Problem constants (fixed by the reference):
//   N_NODES = 2048, N_ELEMS = 4096
//   Output: (N + 2E) x (2E + N) = 10240 x 10240 fp32
#define NN 2048
#define EE 4096
#define WW (2 * EE + NN)   // 10240
#define W4 (WW / 4)        // 2560

// Copy+transpose tiles: 64x64 over M; each writes the kcl copy AND -M^T.
// They come FIRST in the grid so their M reads overlap the fill write stream
// and the kernel tail is pure writes.
#define TP_TILE 64
#define TP_TILES_X (EE / TP_TILE)                     // 64 (e tiles)
#define TP_TILES_Y (NN / TP_TILE)                     // 32 (n tiles)
#define NUM_TP_ITEMS (TP_TILES_X * TP_TILES_Y)        // 2048
// Fill: one block per PAIR of output rows (region boundaries are even, so
// both rows of a pair share a region). 12-20 independent stores per thread.
#define NUM_FILL_BLOCKS (WW / 2)                      // 5120
#define TOTAL_BLOCKS (NUM_TP_ITEMS + NUM_FILL_BLOCKS) // 7168

__global__ void __launch_bounds__(256) fused_kernel(
    const float* __restrict__ M,
    const float* __restrict__ params,
    const int* __restrict__ kinds,
    float* __restrict__ out)
{
    const int bid = blockIdx.x;
    const int tid = threadIdx.x;

    if (bid < NUM_TP_ITEMS) {
        // ------------------------------------------------------------------
        // COPY+TRANSPOSE tile, 64x64 (unchanged R11 winner).
        //   copy : out[n][e]           = M[n][e]
        //   trans: out[NN + e][2E + n] = -M[n][e]
        // ------------------------------------------------------------------
        __shared__ float tile[TP_TILE][TP_TILE + 1];   // [n_local][e_local]

        const int t  = bid;
        const int et = t % TP_TILES_X;
        const int nt = t / TP_TILES_X;
        const int e0 = et * TP_TILE;
        const int n0 = nt * TP_TILE;

        // Batch all 4 loads first (independent -> 4 outstanding LDG.128).
        float4 m4[4];
        #pragma unroll
        for (int j = 0; j < 4; j++) {
            const int idx  = tid + 256 * j;
            const int lrow = idx >> 4;        // n_local 0..63
            const int lc4  = idx & 15;        // e_local/4 0..15
            m4[j] = reinterpret_cast<const float4*>(
                M + (long)(n0 + lrow) * EE + e0)[lc4];
        }

        // kcl copy stores — straight from registers, coalesced.
        #pragma unroll
        for (int j = 0; j < 4; j++) {
            const int idx  = tid + 256 * j;
            const int lrow = idx >> 4;
            const int lc4  = idx & 15;
            reinterpret_cast<float4*>(
                out)[(long)(n0 + lrow) * W4 + (e0 >> 2) + lc4] = m4[j];
        }

        // Stage for transpose.
        #pragma unroll
        for (int j = 0; j < 4; j++) {
            const int idx  = tid + 256 * j;
            const int lrow = idx >> 4;
            const int lc4  = idx & 15;
            tile[lrow][lc4 * 4 + 0] = m4[j].x;
            tile[lrow][lc4 * 4 + 1] = m4[j].y;
            tile[lrow][lc4 * 4 + 2] = m4[j].z;
            tile[lrow][lc4 * 4 + 3] = m4[j].w;
        }
        __syncthreads();

        // Transposed stores: 4 coalesced float4 per thread.
        #pragma unroll
        for (int j = 0; j < 4; j++) {
            const int idx  = tid + 256 * j;
            const int orow = idx >> 4;        // e_local 0..63
            const int oc4  = idx & 15;        // n_local/4 0..15
            const int nl   = oc4 * 4;
            float4 v;
            v.x = -tile[nl + 0][orow];
            v.y = -tile[nl + 1][orow];
            v.z = -tile[nl + 2][orow];
            v.w = -tile[nl + 3][orow];
            reinterpret_cast<float4*>(
                out + (long)(NN + e0 + orow) * WW + 2 * EE + n0)[oc4] = v;
        }
    } else {
        // ------------------------------------------------------------------
        // FILL path: block owns rows (2b, 2b+1) — same region for both.
        // Thread t writes c4 = t + 256*i in each row. Plain float4 stores.
        // ------------------------------------------------------------------
        const int row0 = (bid - NUM_TP_ITEMS) * 2;
        float4* r0 = reinterpret_cast<float4*>(out) + (long)row0 * W4;
        float4* r1 = r0 + W4;
        const float4 zero4 = make_float4(0.f, 0.f, 0.f, 0.f);

        if (row0 < NN) {
            // kcl: [ M | 0 ]. M block (i=0..3) written by tile blocks.
            #pragma unroll
            for (int i = 4; i < 10; i++) {
                r0[tid + 256 * i] = zero4;
                r1[tid + 256 * i] = zero4;
            }
        } else if (row0 < NN + EE) {
            // kvl: [ 0 | I_E | (-M^T by tiles) ]. Write c4 in [0,2048).
            const int ra  = row0 - NN;
            const int da  = EE + ra;            // identity col, row0
            const int db  = da + 1;             // identity col, row1
            const int dc4a = da >> 2, dla = da & 3;
            const int dc4b = db >> 2, dlb = db & 3;
            #pragma unroll
            for (int i = 0; i < 8; i++) {
                const int c4 = tid + 256 * i;
                float4 va = zero4, vb = zero4;
                if (c4 == dc4a) reinterpret_cast<float*>(&va)[dla] = 1.0f;
                if (c4 == dc4b) reinterpret_cast<float*>(&vb)[dlb] = 1.0f;
                r0[c4] = va;
                r1[c4] = vb;
            }
        } else {
            // elem: zeros + z diag at col=pos, y diag at col=E+pos.
            const int pa = row0 - NN - EE;      // pos for row0
            const int pb = pa + 1;              // pos for row1

            const float Pa = params[pa], Pb = params[pb];
            const int   Ka = kinds[pa],  Kb = kinds[pb];

            float za = 0.0f;
            if (Ka == 0)                       za = -Pa;
            else if (Ka == 2)                  za = 1.0f;
            else if (Ka == 3 && !(Pa > 0.0f))  za = 1.0f;
            const float ya = (Ka == 0 || Ka == 1 || (Ka == 3 && Pa > 0.0f)) ? 1.0f : 0.0f;

            float zb = 0.0f;
            if (Kb == 0)                       zb = -Pb;
            else if (Kb == 2)                  zb = 1.0f;
            else if (Kb == 3 && !(Pb > 0.0f))  zb = 1.0f;
            const float yb = (Kb == 0 || Kb == 1 || (Kb == 3 && Pb > 0.0f)) ? 1.0f : 0.0f;

            const int zc4a = pa >> 2, la = pa & 3;
            const int yc4a = (EE + pa) >> 2;     // same sub-lane la
            const int zc4b = pb >> 2, lb = pb & 3;
            const int yc4b = (EE + pb) >> 2;     // same sub-lane lb

            #pragma unroll
            for (int i = 0; i < 10; i++) {
                const int c4 = tid + 256 * i;
                float4 va = zero4, vb = zero4;
                if (c4 == zc4a) reinterpret_cast<float*>(&va)[la] = za;
                if (c4 == yc4a) reinterpret_cast<float*>(&va)[la] = ya;
                if (c4 == zc4b) reinterpret_cast<float*>(&vb)[lb] = zb;
                if (c4 == yc4b) reinterpret_cast<float*>(&vb)[lb] = yb;
                r0[c4] = va;
                r1[c4] = vb;
            }
        }
    }
}

extern "C" void kernel_launch(void* const* d_in, const int* in_sizes, int n_in,
                              void* d_out, int out_size)
{
    const float* M      = (const float*)d_in[0];
    const float* params = (const float*)d_in[1];
    const int*   kinds  = (const int*)d_in[2];
    float*       out    = (float*)d_out;

    (void)in_sizes; (void)n_in; (void)out_size;

    fused_kernel<<<TOTAL_BLOCKS, 256>>>(M, params, kinds, out);
}

// round 14
// speedup vs baseline: 1.0181x; 1.0181x over previous
#include <cuda_runtime.h>

// Problem constants (fixed by the reference):
//   N_NODES = 2048, N_ELEMS = 4096
//   Output: (N + 2E) x (2E + N) = 10240 x 10240 fp32
#define NN 2048
#define EE 4096
#define WW (2 * EE + NN)   // 10240
#define W4 (WW / 4)        // 2560
#define W8 (WW / 8)        // 1280 (32-byte chunks per row)

// Copy+transpose tiles: 64x64 over M; each writes the kcl copy AND -M^T.
// They come FIRST so their M reads overlap the fill write stream and the
// kernel tail is pure writes.
#define TP_TILE 64
#define TP_TILES_X (EE / TP_TILE)                     // 64 (e tiles)
#define TP_TILES_Y (NN / TP_TILE)                     // 32 (n tiles)
#define NUM_TP_ITEMS (TP_TILES_X * TP_TILES_Y)        // 2048
// Fill: one block per output row; 256 threads x 5 chunks of 32B = 1280 = row.
#define NUM_FILL_BLOCKS WW                            // 10240
#define TOTAL_BLOCKS (NUM_TP_ITEMS + NUM_FILL_BLOCKS) // 12288

// 256-bit global store (sm_100 family: STG.E.256).
__device__ __forceinline__ void stg256(float* p, float4 a, float4 b)
{
    asm volatile(
        "st.global.v8.f32 [%0], {%1, %2, %3, %4, %5, %6, %7, %8};"
        :: "l"(p),
           "f"(a.x), "f"(a.y), "f"(a.z), "f"(a.w),
           "f"(b.x), "f"(b.y), "f"(b.z), "f"(b.w)
        : "memory");
}

__global__ void __launch_bounds__(256) fused_kernel(
    const float* __restrict__ M,
    const float* __restrict__ params,
    const int* __restrict__ kinds,
    float* __restrict__ out)
{
    const int bid = blockIdx.x;
    const int tid = threadIdx.x;

    if (bid < NUM_TP_ITEMS) {
        // ------------------------------------------------------------------
        // COPY+TRANSPOSE tile, 64x64 (unchanged R11 winner).
        //   copy : out[n][e]           = M[n][e]
        //   trans: out[NN + e][2E + n] = -M[n][e]
        // ------------------------------------------------------------------
        __shared__ float tile[TP_TILE][TP_TILE + 1];   // [n_local][e_local]

        const int t  = bid;
        const int et = t % TP_TILES_X;
        const int nt = t / TP_TILES_X;
        const int e0 = et * TP_TILE;
        const int n0 = nt * TP_TILE;

        // Batch all 4 loads first (independent -> 4 outstanding LDG.128).
        float4 m4[4];
        #pragma unroll
        for (int j = 0; j < 4; j++) {
            const int idx  = tid + 256 * j;
            const int lrow = idx >> 4;        // n_local 0..63
            const int lc4  = idx & 15;        // e_local/4 0..15
            m4[j] = reinterpret_cast<const float4*>(
                M + (long)(n0 + lrow) * EE + e0)[lc4];
        }

        // kcl copy stores — straight from registers, coalesced.
        #pragma unroll
        for (int j = 0; j < 4; j++) {
            const int idx  = tid + 256 * j;
            const int lrow = idx >> 4;
            const int lc4  = idx & 15;
            reinterpret_cast<float4*>(
                out)[(long)(n0 + lrow) * W4 + (e0 >> 2) + lc4] = m4[j];
        }

        // Stage for transpose.
        #pragma unroll
        for (int j = 0; j < 4; j++) {
            const int idx  = tid + 256 * j;
            const int lrow = idx >> 4;
            const int lc4  = idx & 15;
            tile[lrow][lc4 * 4 + 0] = m4[j].x;
            tile[lrow][lc4 * 4 + 1] = m4[j].y;
            tile[lrow][lc4 * 4 + 2] = m4[j].z;
            tile[lrow][lc4 * 4 + 3] = m4[j].w;
        }
        __syncthreads();

        // Transposed stores: 4 coalesced float4 per thread.
        #pragma unroll
        for (int j = 0; j < 4; j++) {
            const int idx  = tid + 256 * j;
            const int orow = idx >> 4;        // e_local 0..63
            const int oc4  = idx & 15;        // n_local/4 0..15
            const int nl   = oc4 * 4;
            float4 v;
            v.x = -tile[nl + 0][orow];
            v.y = -tile[nl + 1][orow];
            v.z = -tile[nl + 2][orow];
            v.w = -tile[nl + 3][orow];
            reinterpret_cast<float4*>(
                out + (long)(NN + e0 + orow) * WW + 2 * EE + n0)[oc4] = v;
        }
    } else {
        // ------------------------------------------------------------------
        // FILL path: block owns one output row. Thread t writes 32-byte
        // chunk c8 = t + 256*i via STG.256.
        //   kcl : chunks [512,1280)  -> i = 2..4  (M block by tiles)
        //   kvl : chunks [0,1024)    -> i = 0..3  (-M^T by tiles)
        //   elem: chunks [0,1280)    -> i = 0..4
        // ------------------------------------------------------------------
        const int row = bid - NUM_TP_ITEMS;
        float* orow = out + (long)row * WW;
        const float4 z4 = make_float4(0.f, 0.f, 0.f, 0.f);

        if (row < NN) {
            // kcl: [ M | 0 ]
            #pragma unroll
            for (int i = 2; i < 5; i++) {
                stg256(orow + (tid + 256 * i) * 8, z4, z4);
            }
        } else if (row < NN + EE) {
            // kvl: [ 0 | I_E | (-M^T by tiles) ]
            const int r   = row - NN;
            const int d   = EE + r;          // identity column
            const int dc8 = d >> 3;
            const int dl  = d & 7;
            #pragma unroll
            for (int i = 0; i < 4; i++) {
                const int c8 = tid + 256 * i;
                float4 a = z4, b = z4;
                if (c8 == dc8) {
                    if (dl < 4) reinterpret_cast<float*>(&a)[dl]     = 1.0f;
                    else        reinterpret_cast<float*>(&b)[dl - 4] = 1.0f;
                }
                stg256(orow + c8 * 8, a, b);
            }
        } else {
            // elem: zeros + z diag at col=pos, y diag at col=E+pos.
            const int pos = row - NN - EE;
            const float p = params[pos];
            const int   k = kinds[pos];
            float zv = 0.0f;
            if (k == 0)                      zv = -p;   // R
            else if (k == 2)                 zv = 1.0f; // VC
            else if (k == 3 && !(p > 0.0f))  zv = 1.0f; // SW off
            const float yv = (k == 0 || k == 1 || (k == 3 && p > 0.0f)) ? 1.0f : 0.0f;

            const int zc8 = pos >> 3;
            const int yc8 = (EE + pos) >> 3;
            const int l   = pos & 7;         // same sub-lane (EE % 8 == 0)

            #pragma unroll
            for (int i = 0; i < 5; i++) {
                const int c8 = tid + 256 * i;
                float4 a = z4, b = z4;
                if (c8 == zc8) {
                    if (l < 4) reinterpret_cast<float*>(&a)[l]     = zv;
                    else       reinterpret_cast<float*>(&b)[l - 4] = zv;
                }
                if (c8 == yc8) {
                    if (l < 4) reinterpret_cast<float*>(&a)[l]     = yv;
                    else       reinterpret_cast<float*>(&b)[l - 4] = yv;
                }
                stg256(orow + c8 * 8, a, b);
            }
        }
    }
}

extern "C" void kernel_launch(void* const* d_in, const int* in_sizes, int n_in,
                              void* d_out, int out_size)
{
    const float* M      = (const float*)d_in[0];
    const float* params = (const float*)d_in[1];
    const int*   kinds  = (const int*)d_in[2];
    float*       out    = (float*)d_out;

    (void)in_sizes; (void)n_in; (void)out_size;

    fused_kernel<<<TOTAL_BLOCKS, 256>>>(M, params, kinds, out);
}

// round 15
// speedup vs baseline: 1.0338x; 1.0155x over previous
#include <cuda_runtime.h>

// Problem constants (fixed by the reference):
//   N_NODES = 2048, N_ELEMS = 4096
//   Output: (N + 2E) x (2E + N) = 10240 x 10240 fp32
#define NN 2048
#define EE 4096
#define WW (2 * EE + NN)   // 10240
#define W4 (WW / 4)        // 2560

// Copy+transpose tiles: 64x64 over M; each writes the kcl copy AND -M^T.
// They come FIRST so their M reads overlap the fill write stream and the
// kernel tail is pure writes.
#define TP_TILE 64
#define TP_TILES_X (EE / TP_TILE)                     // 64 (e tiles)
#define TP_TILES_Y (NN / TP_TILE)                     // 32 (n tiles)
#define NUM_TP_ITEMS (TP_TILES_X * TP_TILES_Y)        // 2048
// Fill: one block per output row; 256 threads x 5 chunks of 32B = row.
#define NUM_FILL_BLOCKS WW                            // 10240
#define TOTAL_BLOCKS (NUM_TP_ITEMS + NUM_FILL_BLOCKS) // 12288

// 256-bit global store (sm_100 family: STG.E.256).
__device__ __forceinline__ void stg256(float* p, float4 a, float4 b)
{
    asm volatile(
        "st.global.v8.f32 [%0], {%1, %2, %3, %4, %5, %6, %7, %8};"
        :: "l"(p),
           "f"(a.x), "f"(a.y), "f"(a.z), "f"(a.w),
           "f"(b.x), "f"(b.y), "f"(b.z), "f"(b.w)
        : "memory");
}

__global__ void __launch_bounds__(256) fused_kernel(
    const float* __restrict__ M,
    const float* __restrict__ params,
    const int* __restrict__ kinds,
    float* __restrict__ out)
{
    const int bid = blockIdx.x;
    const int tid = threadIdx.x;

    if (bid < NUM_TP_ITEMS) {
        // ------------------------------------------------------------------
        // COPY+TRANSPOSE tile, 64x64, 256-bit chunked.
        //   copy : out[n][e]           = M[n][e]
        //   trans: out[NN + e][2E + n] = -M[n][e]
        // Per thread: 2 chunks of 8 floats (idx = tid, tid+256; 512 chunks
        // cover 64 rows x 8 chunks).
        // ------------------------------------------------------------------
        __shared__ float tile[TP_TILE][TP_TILE + 1];   // [n_local][e_local]

        const int t  = bid;
        const int et = t % TP_TILES_X;
        const int nt = t / TP_TILES_X;
        const int e0 = et * TP_TILE;
        const int n0 = nt * TP_TILE;

        // Batch all 4 float4 loads first (independent -> MLP 4).
        float4 a[2], b[2];
        #pragma unroll
        for (int j = 0; j < 2; j++) {
            const int idx  = tid + 256 * j;
            const int lrow = idx >> 3;        // n_local 0..63
            const int lc8  = idx & 7;         // e chunk 0..7
            const float4* src = reinterpret_cast<const float4*>(
                M + (long)(n0 + lrow) * EE + e0 + lc8 * 8);
            a[j] = src[0];
            b[j] = src[1];
        }

        // kcl copy stores — straight from registers, STG.256, coalesced.
        #pragma unroll
        for (int j = 0; j < 2; j++) {
            const int idx  = tid + 256 * j;
            const int lrow = idx >> 3;
            const int lc8  = idx & 7;
            stg256(out + (long)(n0 + lrow) * WW + e0 + lc8 * 8, a[j], b[j]);
        }

        // Stage for transpose.
        #pragma unroll
        for (int j = 0; j < 2; j++) {
            const int idx  = tid + 256 * j;
            const int lrow = idx >> 3;
            const int ec   = (idx & 7) * 8;
            tile[lrow][ec + 0] = a[j].x;
            tile[lrow][ec + 1] = a[j].y;
            tile[lrow][ec + 2] = a[j].z;
            tile[lrow][ec + 3] = a[j].w;
            tile[lrow][ec + 4] = b[j].x;
            tile[lrow][ec + 5] = b[j].y;
            tile[lrow][ec + 6] = b[j].z;
            tile[lrow][ec + 7] = b[j].w;
        }
        __syncthreads();

        // Transposed stores: 2 STG.256 per thread, coalesced.
        #pragma unroll
        for (int j = 0; j < 2; j++) {
            const int idx  = tid + 256 * j;
            const int orow = idx >> 3;        // e_local 0..63
            const int nl   = (idx & 7) * 8;   // n_local base 0..56
            float4 va, vb;
            va.x = -tile[nl + 0][orow];
            va.y = -tile[nl + 1][orow];
            va.z = -tile[nl + 2][orow];
            va.w = -tile[nl + 3][orow];
            vb.x = -tile[nl + 4][orow];
            vb.y = -tile[nl + 5][orow];
            vb.z = -tile[nl + 6][orow];
            vb.w = -tile[nl + 7][orow];
            stg256(out + (long)(NN + e0 + orow) * WW + 2 * EE + n0 + nl, va, vb);
        }
    } else {
        // ------------------------------------------------------------------
        // FILL path (unchanged R14 winner): block owns one output row.
        // Thread t writes 32-byte chunk c8 = t + 256*i via STG.256.
        //   kcl : chunks i = 2..4  (M block by tiles)
        //   kvl : chunks i = 0..3  (-M^T by tiles)
        //   elem: chunks i = 0..4
        // ------------------------------------------------------------------
        const int row = bid - NUM_TP_ITEMS;
        float* orow = out + (long)row * WW;
        const float4 z4 = make_float4(0.f, 0.f, 0.f, 0.f);

        if (row < NN) {
            // kcl: [ M | 0 ]
            #pragma unroll
            for (int i = 2; i < 5; i++) {
                stg256(orow + (tid + 256 * i) * 8, z4, z4);
            }
        } else if (row < NN + EE) {
            // kvl: [ 0 | I_E | (-M^T by tiles) ]
            const int r   = row - NN;
            const int d   = EE + r;          // identity column
            const int dc8 = d >> 3;
            const int dl  = d & 7;
            #pragma unroll
            for (int i = 0; i < 4; i++) {
                const int c8 = tid + 256 * i;
                float4 aa = z4, bb = z4;
                if (c8 == dc8) {
                    if (dl < 4) reinterpret_cast<float*>(&aa)[dl]     = 1.0f;
                    else        reinterpret_cast<float*>(&bb)[dl - 4] = 1.0f;
                }
                stg256(orow + c8 * 8, aa, bb);
            }
        } else {
            // elem: zeros + z diag at col=pos, y diag at col=E+pos.
            const int pos = row - NN - EE;
            const float p = params[pos];
            const int   k = kinds[pos];
            float zv = 0.0f;
            if (k == 0)                      zv = -p;   // R
            else if (k == 2)                 zv = 1.0f; // VC
            else if (k == 3 && !(p > 0.0f))  zv = 1.0f; // SW off
            const float yv = (k == 0 || k == 1 || (k == 3 && p > 0.0f)) ? 1.0f : 0.0f;

            const int zc8 = pos >> 3;
            const int yc8 = (EE + pos) >> 3;
            const int l   = pos & 7;         // same sub-lane (EE % 8 == 0)

            #pragma unroll
            for (int i = 0; i < 5; i++) {
                const int c8 = tid + 256 * i;
                float4 aa = z4, bb = z4;
                if (c8 == zc8) {
                    if (l < 4) reinterpret_cast<float*>(&aa)[l]     = zv;
                    else       reinterpret_cast<float*>(&bb)[l - 4] = zv;
                }
                if (c8 == yc8) {
                    if (l < 4) reinterpret_cast<float*>(&aa)[l]     = yv;
                    else       reinterpret_cast<float*>(&bb)[l - 4] = yv;
                }
                stg256(orow + c8 * 8, aa, bb);
            }
        }
    }
}

extern "C" void kernel_launch(void* const* d_in, const int* in_sizes, int n_in,
                              void* d_out, int out_size)
{
    const float* M      = (const float*)d_in[0];
    const float* params = (const float*)d_in[1];
    const int*   kinds  = (const int*)d_in[2];
    float*       out    = (float*)d_out;

    (void)in_sizes; (void)n_in; (void)out_size;

    fused_kernel<<<TOTAL_BLOCKS, 256>>>(M, params, kinds, out);
}